// round 3
// baseline (speedup 1.0000x reference)
#include <cuda_runtime.h>
#include <cstdint>

#define PP   8       // personas
#define FF   64      // factor dim (floats per item row)
#define SB   200     // S (items per batch row)
#define TPB  224     // 7 warps
#define RPB  2       // batch rows per CTA
#define NF4  (RPB * SB * (FF/4))   // 6400 float4 gather elements per CTA

// packed f32x2 FMA (Blackwell): d = a*b + c on 2 lanes of f32 in a b64 reg
__device__ __forceinline__ unsigned long long fma2(unsigned long long a,
                                                   unsigned long long b,
                                                   unsigned long long c) {
    unsigned long long d;
    asm("fma.rn.f32x2 %0, %1, %2, %3;" : "=l"(d) : "l"(a), "l"(b), "l"(c));
    return d;
}

// 16B shared load into two b64 packed-f32x2 regs
__device__ __forceinline__ void lds16(unsigned long long& a, unsigned long long& b,
                                      uint32_t addr) {
    asm volatile("ld.shared.v2.b64 {%0,%1}, [%2];" : "=l"(a), "=l"(b) : "r"(addr));
}

__device__ __forceinline__ float hsum2(unsigned long long a) {
    return __uint_as_float((unsigned)a) + __uint_as_float((unsigned)(a >> 32));
}

__global__ __launch_bounds__(TPB, 2) void cf_kernel(
    const int*   __restrict__ user,     // [B]
    const int*   __restrict__ items,    // [B,SB]
    const float* __restrict__ ufac,     // [N_USERS, PP, FF]
    const float* __restrict__ ifac,     // [N_ITEMS, FF]
    float*       __restrict__ pred,     // [B,SB]
    float*       __restrict__ scores,   // [B,SB,PP]
    int B)
{
    __shared__ __align__(16) float s_u[RPB * PP * FF];  // 4 KB
    extern __shared__ __align__(16) float s_v[];        // RPB*SB*FF floats, XOR-swizzled

    const int tid = threadIdx.x;
    const long long b0 = (long long)blockIdx.x * RPB;

    // ---- Stage u for both batches: 256 float4, coalesced ----
    {
        const long long ubase0 = (long long)__ldg(&user[b0]) * (PP * FF);
        const long long ubase1 = (long long)__ldg(&user[b0 + 1]) * (PP * FF);
        #pragma unroll
        for (int i = tid; i < RPB * PP * FF / 4; i += TPB) {
            const long long src = (i < 128 ? ubase0 : ubase1) + (long long)(i & 127) * 4;
            ((float4*)s_u)[i] = *(const float4*)(ufac + src);
        }
    }

    // ---- Gather v rows: flat float4 index, low register footprint ----
    // element i: row = i>>4 (0..399), chunk c = i&15; swizzled phys chunk = c ^ (row&15)
    const int* itr = items + b0 * SB;
    #pragma unroll 4
    for (int i = tid; i < NF4; i += TPB) {
        const int r = i >> 4;
        const int c = i & 15;
        const int idx = __ldg(&itr[r]);
        const float4 v4 = *(const float4*)(ifac + (long long)idx * FF + (c << 2));
        *(float4*)(s_v + r * FF + ((c ^ (r & 15)) << 2)) = v4;
    }
    __syncthreads();

    // ---- Compute: thread t<200 handles rows (s0, s0+100) of batch bb ----
    if (tid < RPB * 100) {
        const int bb = tid / 100;
        const int s0 = tid - bb * 100;
        const int r0 = bb * SB + s0;
        const int r1 = r0 + 100;
        const long long b = b0 + bb;

        const uint32_t sv = (uint32_t)__cvta_generic_to_shared(s_v);
        const uint32_t su = (uint32_t)__cvta_generic_to_shared(s_u) + bb * (PP * FF * 4);
        const uint32_t v0a = sv + r0 * (FF * 4);
        const uint32_t v1a = sv + r1 * (FF * 4);
        const int m0 = r0 & 15;
        const int m1 = r1 & 15;

        unsigned long long acc0[PP], acc1[PP];
        #pragma unroll
        for (int p = 0; p < PP; p++) { acc0[p] = 0ull; acc1[p] = 0ull; }

        #pragma unroll
        for (int cc = 0; cc < FF / 4; cc++) {
            unsigned long long v0x, v0y, v1x, v1y;
            lds16(v0x, v0y, v0a + ((cc ^ m0) << 4));
            lds16(v1x, v1y, v1a + ((cc ^ m1) << 4));
            #pragma unroll
            for (int p = 0; p < PP; p++) {
                unsigned long long ux, uy;
                lds16(ux, uy, su + p * (FF * 4) + (cc << 4));   // broadcast
                acc0[p] = fma2(v0x, ux, acc0[p]);
                acc0[p] = fma2(v0y, uy, acc0[p]);
                acc1[p] = fma2(v1x, ux, acc1[p]);
                acc1[p] = fma2(v1y, uy, acc1[p]);
            }
        }

        // softmax over 8 personas + pred = sum_p a_p * r_p
        #pragma unroll 2
        for (int h = 0; h < 2; h++) {
            const unsigned long long* accp = (h == 0) ? acc0 : acc1;
            const int s = s0 + h * 100;

            float r[PP];
            #pragma unroll
            for (int p = 0; p < PP; p++) r[p] = hsum2(accp[p]);

            float m = r[0];
            #pragma unroll
            for (int p = 1; p < PP; p++) m = fmaxf(m, r[p]);
            float e[PP], sum = 0.f;
            #pragma unroll
            for (int p = 0; p < PP; p++) { e[p] = __expf(r[p] - m); sum += e[p]; }
            const float inv = 1.f / sum;

            float a[PP], pr = 0.f;
            #pragma unroll
            for (int p = 0; p < PP; p++) { a[p] = e[p] * inv; pr = fmaf(a[p], r[p], pr); }

            pred[b * SB + s] = pr;
            float4* so = (float4*)(scores + (b * SB + s) * (long long)PP);
            so[0] = make_float4(a[0], a[1], a[2], a[3]);
            so[1] = make_float4(a[4], a[5], a[6], a[7]);
        }
    }
}

extern "C" void kernel_launch(void* const* d_in, const int* in_sizes, int n_in,
                              void* d_out, int out_size) {
    const int*   user  = (const int*)d_in[0];
    const int*   items = (const int*)d_in[1];
    const float* ufac  = (const float*)d_in[2];
    const float* ifac  = (const float*)d_in[3];

    const int B = in_sizes[0];

    float* out    = (float*)d_out;
    float* pred   = out;                        // [B,SB]
    float* scores = out + (long long)B * SB;    // [B,SB,PP]

    const int smem = RPB * SB * FF * (int)sizeof(float);   // 102,400 B
    cudaFuncSetAttribute(cf_kernel, cudaFuncAttributeMaxDynamicSharedMemorySize, smem);

    const int grid = (B + RPB - 1) / RPB;
    cf_kernel<<<grid, TPB, smem>>>(user, items, ufac, ifac, pred, scores, B);
}

// round 4
// speedup vs baseline: 1.0195x; 1.0195x over previous
#include <cuda_runtime.h>
#include <cstdint>

#define PP  8      // personas
#define FF  64     // factor dim
#define SB  200    // items per batch row
#define HB  100    // thread handles 2 adjacent s
#define TPB 256
#define NU  4      // users staged per block (block spans <= 4 b values)

typedef unsigned long long ull;

// packed f32x2 FMA (Blackwell)
__device__ __forceinline__ ull fma2(ull a, ull b, ull c) {
    ull d;
    asm("fma.rn.f32x2 %0, %1, %2, %3;" : "=l"(d) : "l"(a), "l"(b), "l"(c));
    return d;
}
__device__ __forceinline__ float hsum2(ull a) {
    return __uint_as_float((unsigned)a) + __uint_as_float((unsigned)(a >> 32));
}
__device__ __forceinline__ ull d2u(double d) { return (ull)__double_as_longlong(d); }

__global__ __launch_bounds__(TPB, 2) void cf_kernel(
    const int*   __restrict__ user,     // [B]
    const int*   __restrict__ items,    // [B,SB]
    const float* __restrict__ ufac,     // [N_USERS, PP, FF]
    const float* __restrict__ ifac,     // [N_ITEMS, FF]
    float*       __restrict__ pred,     // [B,SB]
    float*       __restrict__ scores,   // [B,SB,PP]
    int B)
{
    __shared__ __align__(16) float s_u[NU * PP * FF];   // 8 KB

    const int tid = threadIdx.x;
    const long long j = (long long)blockIdx.x * TPB + tid;   // over B*HB
    const int bfirst = (int)(((long long)blockIdx.x * TPB) / HB);

    // ---- Stage u for up to NU users (512 float4, 2 per thread) ----
    #pragma unroll
    for (int i = tid; i < NU * PP * FF / 4; i += TPB) {
        const int uu  = i >> 7;          // user slot (128 float4 each)
        const int off = i & 127;
        int bb = bfirst + uu; if (bb >= B) bb = B - 1;
        const long long ub = (long long)__ldg(&user[bb]) * (PP * FF);
        ((float4*)s_u)[i] = __ldg((const float4*)(ufac + ub) + off);
    }

    const long long total = (long long)B * HB;
    const bool ok = (j < total);
    const int b  = ok ? (int)(j / HB) : (B - 1);
    const int s2 = ok ? (int)(j % HB) : 0;

    // two adjacent item indices (one LDG.64)
    const int2 idx = *(const int2*)(items + (long long)b * SB + 2 * s2);
    const double2* v0p = (const double2*)(ifac + (long long)idx.x * FF);
    const double2* v1p = (const double2*)(ifac + (long long)idx.y * FF);

    // prefetch chunk 0 (16 floats per row = 2 double2 loads... 4 x 16B? -> 4 double2? )
    // chunk = 16 floats = 64B = 4 double2? No: double2 = 16B = 4 floats. chunk = 4 double2.
    double2 cur0[4], cur1[4], nxt0[4], nxt1[4];
    #pragma unroll
    for (int k = 0; k < 4; k++) { cur0[k] = __ldg(v0p + k); cur1[k] = __ldg(v1p + k); }

    __syncthreads();

    const float* su = s_u + (b - bfirst) * (PP * FF);

    ull acc0[PP], acc1[PP];
    #pragma unroll
    for (int p = 0; p < PP; p++) { acc0[p] = 0ull; acc1[p] = 0ull; }

    #pragma unroll
    for (int c = 0; c < 4; c++) {
        if (c < 3) {
            #pragma unroll
            for (int k = 0; k < 4; k++) {
                nxt0[k] = __ldg(v0p + (c + 1) * 4 + k);
                nxt1[k] = __ldg(v1p + (c + 1) * 4 + k);
            }
        }
        #pragma unroll
        for (int k = 0; k < 4; k++) {
            const ull v0x = d2u(cur0[k].x), v0y = d2u(cur0[k].y);
            const ull v1x = d2u(cur1[k].x), v1y = d2u(cur1[k].y);
            #pragma unroll
            for (int p = 0; p < PP; p++) {
                const double2 u2 = *(const double2*)(su + p * FF + c * 16 + k * 4); // LDS.128 broadcast
                const ull ux = d2u(u2.x), uy = d2u(u2.y);
                acc0[p] = fma2(v0x, ux, acc0[p]);
                acc0[p] = fma2(v0y, uy, acc0[p]);
                acc1[p] = fma2(v1x, ux, acc1[p]);
                acc1[p] = fma2(v1y, uy, acc1[p]);
            }
        }
        if (c < 3) {
            #pragma unroll
            for (int k = 0; k < 4; k++) { cur0[k] = nxt0[k]; cur1[k] = nxt1[k]; }
        }
    }

    if (ok) {
        // softmax over 8 personas + pred = sum_p a_p * r_p  (Σ a_p r_p == attentive_user·v)
        float pr2[2];
        float a0[PP], a1[PP];
        #pragma unroll 2
        for (int h = 0; h < 2; h++) {
            const ull* accp = (h == 0) ? acc0 : acc1;
            float* av = (h == 0) ? a0 : a1;
            float r[PP];
            #pragma unroll
            for (int p = 0; p < PP; p++) r[p] = hsum2(accp[p]);
            float m = r[0];
            #pragma unroll
            for (int p = 1; p < PP; p++) m = fmaxf(m, r[p]);
            float e[PP], sum = 0.f;
            #pragma unroll
            for (int p = 0; p < PP; p++) { e[p] = __expf(r[p] - m); sum += e[p]; }
            const float inv = 1.f / sum;
            float pr = 0.f;
            #pragma unroll
            for (int p = 0; p < PP; p++) { av[p] = e[p] * inv; pr = fmaf(av[p], r[p], pr); }
            pr2[h] = pr;
        }

        const long long sbase = (long long)b * SB + 2 * s2;
        *(float2*)(pred + sbase) = make_float2(pr2[0], pr2[1]);

        float4* so = (float4*)(scores + sbase * PP);
        so[0] = make_float4(a0[0], a0[1], a0[2], a0[3]);
        so[1] = make_float4(a0[4], a0[5], a0[6], a0[7]);
        so[2] = make_float4(a1[0], a1[1], a1[2], a1[3]);
        so[3] = make_float4(a1[4], a1[5], a1[6], a1[7]);
    }
}

extern "C" void kernel_launch(void* const* d_in, const int* in_sizes, int n_in,
                              void* d_out, int out_size) {
    const int*   user  = (const int*)d_in[0];
    const int*   items = (const int*)d_in[1];
    const float* ufac  = (const float*)d_in[2];
    const float* ifac  = (const float*)d_in[3];

    const int B = in_sizes[0];

    float* out    = (float*)d_out;
    float* pred   = out;                        // [B,SB]
    float* scores = out + (long long)B * SB;    // [B,SB,PP]

    const long long total = (long long)B * HB;
    const int grid = (int)((total + TPB - 1) / TPB);
    cf_kernel<<<grid, TPB>>>(user, items, ufac, ifac, pred, scores, B);
}